// round 4
// baseline (speedup 1.0000x reference)
#include <cuda_runtime.h>
#include <cuda_bf16.h>
#include <math.h>

// Problem constants
#define Bb 4
#define Tt 2048
#define Cc 1024
#define Hh 16
#define Dd 64
#define Mrows (Bb * Tt)        // 8192
#define YSZ   ((size_t)Bb * Tt * Cc)         // 8,388,608
#define KVSZ  ((size_t)Bb * Hh * Tt * Dd)    // 8,388,608

// Scratch (allocation-free rule: __device__ globals)
__device__ float g_q[(size_t)Mrows * Cc];   // Q in (B,H,T,D)
__device__ float g_y[(size_t)Mrows * Cc];   // attention output, (B,T,C) row-major

// ---------------------------------------------------------------------------
// SGEMM: out = A(8192x1024) @ W(1024x1024) + bias
// BM=BN=128, BK=16, 256 threads, 8x8 per thread.
// out_mode 0: row-major (B*T, C). out_mode 1: scatter to (B,H,T,D).
// ---------------------------------------------------------------------------
__global__ __launch_bounds__(256)
void sgemm128(const float* __restrict__ A, const float* __restrict__ W,
              const float* __restrict__ bias, float* __restrict__ out,
              int out_mode)
{
    __shared__ float As[16][132];   // A^T tile, padded
    __shared__ float Bs[16][128];

    const int tid = threadIdx.x;
    const int bx = blockIdx.x;      // N block (0..7)
    const int by = blockIdx.y;      // M block (0..63)

    const float* Ab = A + (size_t)by * 128 * Cc;
    const float* Wb = W + bx * 128;

    const int row0 = (tid >> 4) * 8;
    const int col0 = (tid & 15) * 8;

    float acc[8][8];
    #pragma unroll
    for (int i = 0; i < 8; i++)
        #pragma unroll
        for (int j = 0; j < 8; j++) acc[i][j] = 0.f;

    for (int kt = 0; kt < Cc; kt += 16) {
        // Load A tile (128x16), transpose into As
        #pragma unroll
        for (int l = 0; l < 2; l++) {
            int s  = tid + l * 256;          // 0..511 float4 slots
            int ar = s >> 2;
            int ac = (s & 3) * 4;
            float4 t = *(const float4*)(Ab + (size_t)ar * Cc + kt + ac);
            As[ac + 0][ar] = t.x;
            As[ac + 1][ar] = t.y;
            As[ac + 2][ar] = t.z;
            As[ac + 3][ar] = t.w;
        }
        // Load W tile (16x128)
        #pragma unroll
        for (int l = 0; l < 2; l++) {
            int s  = tid + l * 256;
            int br = s >> 5;
            int bc = (s & 31) * 4;
            *(float4*)(&Bs[br][bc]) = *(const float4*)(Wb + (size_t)(kt + br) * Cc + bc);
        }
        __syncthreads();

        #pragma unroll
        for (int kk = 0; kk < 16; kk++) {
            float a[8], b[8];
            *(float4*)(a)     = *(const float4*)(&As[kk][row0]);
            *(float4*)(a + 4) = *(const float4*)(&As[kk][row0 + 4]);
            *(float4*)(b)     = *(const float4*)(&Bs[kk][col0]);
            *(float4*)(b + 4) = *(const float4*)(&Bs[kk][col0 + 4]);
            #pragma unroll
            for (int i = 0; i < 8; i++)
                #pragma unroll
                for (int j = 0; j < 8; j++)
                    acc[i][j] += a[i] * b[j];
        }
        __syncthreads();
    }

    const int gm0 = by * 128 + row0;
    const int gn0 = bx * 128 + col0;
    float bv[8];
    #pragma unroll
    for (int j = 0; j < 8; j++) bv[j] = bias[gn0 + j];

    if (out_mode == 0) {
        #pragma unroll
        for (int i = 0; i < 8; i++) {
            int m = gm0 + i;
            float4 w0 = make_float4(acc[i][0] + bv[0], acc[i][1] + bv[1],
                                    acc[i][2] + bv[2], acc[i][3] + bv[3]);
            float4 w1 = make_float4(acc[i][4] + bv[4], acc[i][5] + bv[5],
                                    acc[i][6] + bv[6], acc[i][7] + bv[7]);
            *(float4*)(out + (size_t)m * Cc + gn0)     = w0;
            *(float4*)(out + (size_t)m * Cc + gn0 + 4) = w1;
        }
    } else {
        // scatter to (B,H,T,D): m = b*T + t ; n = h*D + d (8 cols stay in one h)
        const int h  = gn0 >> 6;
        const int d0 = gn0 & 63;
        #pragma unroll
        for (int i = 0; i < 8; i++) {
            int m = gm0 + i;
            int b = m >> 11;          // /T
            int t = m & 2047;         // %T
            size_t base = (((size_t)(b * Hh + h)) * Tt + t) * Dd + d0;
            float4 w0 = make_float4(acc[i][0] + bv[0], acc[i][1] + bv[1],
                                    acc[i][2] + bv[2], acc[i][3] + bv[3]);
            float4 w1 = make_float4(acc[i][4] + bv[4], acc[i][5] + bv[5],
                                    acc[i][6] + bv[6], acc[i][7] + bv[7]);
            *(float4*)(out + base)     = w0;
            *(float4*)(out + base + 4) = w1;
        }
    }
}

// ---------------------------------------------------------------------------
// Flash attention (fp32, causal). One CTA = 64 query rows of one (b,h).
// 256 threads as 16x16; each thread owns 4 rows x 4 cols.
// Dynamic smem: Q,K,V,P tiles @ 64x68 floats = 69,632 bytes.
// ---------------------------------------------------------------------------
#define LDT 68
__global__ __launch_bounds__(256)
void attn_kernel(const float* __restrict__ q, const float* __restrict__ k,
                 const float* __restrict__ v, float* __restrict__ y)
{
    extern __shared__ float sm[];
    float* Qs = sm;
    float* Ks = Qs + 64 * LDT;
    float* Vs = Ks + 64 * LDT;
    float* Ps = Vs + 64 * LDT;

    const int qb  = blockIdx.x;       // query tile (0..31)
    const int bh  = blockIdx.y;       // 0..63
    const int tid = threadIdx.x;
    const int tx  = tid & 15;
    const int ty  = tid >> 4;
    const int r0  = ty * 4;
    const int c0  = tx * 4;

    const float* qp = q + ((size_t)bh * Tt + qb * 64) * Dd;
    const float* kp = k + (size_t)bh * Tt * Dd;
    const float* vp = v + (size_t)bh * Tt * Dd;

    // Load Q tile (64x64)
    for (int i = tid; i < 64 * 16; i += 256) {
        int row = i >> 4, c4 = (i & 15) * 4;
        *(float4*)(Qs + row * LDT + c4) = *(const float4*)(qp + row * Dd + c4);
    }

    float o[4][4];
    float m_i[4], l_i[4];
    #pragma unroll
    for (int i = 0; i < 4; i++) {
        m_i[i] = -INFINITY; l_i[i] = 0.f;
        #pragma unroll
        for (int j = 0; j < 4; j++) o[i][j] = 0.f;
    }

    for (int jt = 0; jt <= qb; jt++) {
        __syncthreads();   // protect Ks/Vs/Ps from previous iteration readers
        for (int i = tid; i < 64 * 16; i += 256) {
            int row = i >> 4, c4 = (i & 15) * 4;
            *(float4*)(Ks + row * LDT + c4) = *(const float4*)(kp + (size_t)(jt * 64 + row) * Dd + c4);
            *(float4*)(Vs + row * LDT + c4) = *(const float4*)(vp + (size_t)(jt * 64 + row) * Dd + c4);
        }
        __syncthreads();

        // S = Q K^T
        float s[4][4];
        #pragma unroll
        for (int i = 0; i < 4; i++)
            #pragma unroll
            for (int j = 0; j < 4; j++) s[i][j] = 0.f;

        #pragma unroll 4
        for (int d4 = 0; d4 < 64; d4 += 4) {
            float4 qv[4], kv[4];
            #pragma unroll
            for (int i = 0; i < 4; i++) qv[i] = *(const float4*)(Qs + (r0 + i) * LDT + d4);
            #pragma unroll
            for (int j = 0; j < 4; j++) kv[j] = *(const float4*)(Ks + (c0 + j) * LDT + d4);
            #pragma unroll
            for (int i = 0; i < 4; i++)
                #pragma unroll
                for (int j = 0; j < 4; j++)
                    s[i][j] += qv[i].x * kv[j].x + qv[i].y * kv[j].y
                             + qv[i].z * kv[j].z + qv[i].w * kv[j].w;
        }

        const float scale = 0.125f;   // 1/sqrt(64)
        #pragma unroll
        for (int i = 0; i < 4; i++)
            #pragma unroll
            for (int j = 0; j < 4; j++) s[i][j] *= scale;

        if (jt == qb) {
            #pragma unroll
            for (int i = 0; i < 4; i++)
                #pragma unroll
                for (int j = 0; j < 4; j++)
                    if (c0 + j > r0 + i) s[i][j] = -INFINITY;
        }

        // Online softmax (row state replicated across the 16 tx threads)
        #pragma unroll
        for (int i = 0; i < 4; i++) {
            float mx = fmaxf(fmaxf(s[i][0], s[i][1]), fmaxf(s[i][2], s[i][3]));
            #pragma unroll
            for (int off = 8; off >= 1; off >>= 1)
                mx = fmaxf(mx, __shfl_xor_sync(0xffffffffu, mx, off, 16));
            float mnew  = fmaxf(m_i[i], mx);
            float alpha = __expf(m_i[i] - mnew);
            float sum = 0.f;
            #pragma unroll
            for (int j = 0; j < 4; j++) {
                s[i][j] = __expf(s[i][j] - mnew);
                sum += s[i][j];
            }
            #pragma unroll
            for (int off = 8; off >= 1; off >>= 1)
                sum += __shfl_xor_sync(0xffffffffu, sum, off, 16);
            l_i[i] = l_i[i] * alpha + sum;
            m_i[i] = mnew;
            #pragma unroll
            for (int j = 0; j < 4; j++) o[i][j] *= alpha;
        }

        // Stage P
        #pragma unroll
        for (int i = 0; i < 4; i++)
            *(float4*)(Ps + (r0 + i) * LDT + c0) =
                make_float4(s[i][0], s[i][1], s[i][2], s[i][3]);
        __syncthreads();

        // O += P @ V
        #pragma unroll 4
        for (int kv4 = 0; kv4 < 64; kv4 += 4) {
            float4 pr[4], vr[4];
            #pragma unroll
            for (int i = 0; i < 4; i++) pr[i] = *(const float4*)(Ps + (r0 + i) * LDT + kv4);
            #pragma unroll
            for (int t2 = 0; t2 < 4; t2++) vr[t2] = *(const float4*)(Vs + (kv4 + t2) * LDT + c0);
            #pragma unroll
            for (int i = 0; i < 4; i++) {
                o[i][0] += pr[i].x * vr[0].x + pr[i].y * vr[1].x + pr[i].z * vr[2].x + pr[i].w * vr[3].x;
                o[i][1] += pr[i].x * vr[0].y + pr[i].y * vr[1].y + pr[i].z * vr[2].y + pr[i].w * vr[3].y;
                o[i][2] += pr[i].x * vr[0].z + pr[i].y * vr[1].z + pr[i].z * vr[2].z + pr[i].w * vr[3].z;
                o[i][3] += pr[i].x * vr[0].w + pr[i].y * vr[1].w + pr[i].z * vr[2].w + pr[i].w * vr[3].w;
            }
        }
    }

    // Epilogue: y[b, t, h*D + d] = O / l
    const int b = bh >> 4;
    const int h = bh & 15;
    #pragma unroll
    for (int i = 0; i < 4; i++) {
        int t = qb * 64 + r0 + i;
        float inv = 1.0f / l_i[i];
        float4 w = make_float4(o[i][0] * inv, o[i][1] * inv,
                               o[i][2] * inv, o[i][3] * inv);
        *(float4*)(y + ((size_t)(b * Tt + t)) * Cc + h * Dd + c0) = w;
    }
}

// ---------------------------------------------------------------------------
extern "C" void kernel_launch(void* const* d_in, const int* in_sizes, int n_in,
                              void* d_out, int out_size)
{
    const float* x  = (const float*)d_in[0];
    const float* wq = (const float*)d_in[1];
    const float* bq = (const float*)d_in[2];
    const float* wk = (const float*)d_in[3];
    const float* bk = (const float*)d_in[4];
    const float* wv = (const float*)d_in[5];
    const float* bv = (const float*)d_in[6];
    const float* wp = (const float*)d_in[7];
    const float* bp = (const float*)d_in[8];

    float* out   = (float*)d_out;
    float* y_out = out;                 // (B,T,C)
    float* k_out = out + YSZ;           // present[0] = k, (B,H,T,D)
    float* v_out = out + YSZ + KVSZ;    // present[1] = v

    float* qbuf;  cudaGetSymbolAddress((void**)&qbuf, g_q);
    float* ybuf;  cudaGetSymbolAddress((void**)&ybuf, g_y);

    cudaFuncSetAttribute(attn_kernel,
                         cudaFuncAttributeMaxDynamicSharedMemorySize,
                         4 * 64 * LDT * (int)sizeof(float));

    dim3 gG(Cc / 128, Mrows / 128);     // (8, 64)
    sgemm128<<<gG, 256>>>(x, wq, bq, qbuf, 1);
    sgemm128<<<gG, 256>>>(x, wk, bk, k_out, 1);
    sgemm128<<<gG, 256>>>(x, wv, bv, v_out, 1);

    dim3 gA(Tt / 64, Bb * Hh);          // (32, 64)
    attn_kernel<<<gA, 256, 4 * 64 * LDT * sizeof(float)>>>(qbuf, k_out, v_out, ybuf);

    sgemm128<<<gG, 256>>>(ybuf, wp, bp, y_out, 0);
}

// round 8
// speedup vs baseline: 1.2735x; 1.2735x over previous
#include <cuda_runtime.h>
#include <cuda_bf16.h>
#include <math.h>

// Problem constants
#define Bb 4
#define Tt 2048
#define Cc 1024
#define Hh 16
#define Dd 64
#define Mrows (Bb * Tt)        // 8192
#define YSZ   ((size_t)Bb * Tt * Cc)         // 8,388,608
#define KVSZ  ((size_t)Bb * Hh * Tt * Dd)    // 8,388,608

// Scratch (allocation-free rule: __device__ globals)
__device__ float g_q[(size_t)Mrows * Cc];   // Q in (B,H,T,D)
__device__ float g_y[(size_t)Mrows * Cc];   // attention output, (B,T,C) row-major

// ---------------------------------------------------------------------------
// Packed fp32x2 helpers (Blackwell FFMA2 path — only reachable via PTX)
// ---------------------------------------------------------------------------
typedef unsigned long long u64t;
union F2 { u64t u; float f[2]; };

__device__ __forceinline__ u64t pk(float x) {
    u64t r; asm("mov.b64 %0, {%1, %1};" : "=l"(r) : "f"(x)); return r;
}
__device__ __forceinline__ u64t pk2(float x, float y) {
    u64t r; asm("mov.b64 %0, {%1, %2};" : "=l"(r) : "f"(x), "f"(y)); return r;
}
__device__ __forceinline__ void fma2(u64t& d, u64t a, u64t b) {
    asm("fma.rn.f32x2 %0, %1, %2, %0;" : "+l"(d) : "l"(a), "l"(b));
}
__device__ __forceinline__ void mul2(u64t& d, u64t a) {
    asm("mul.rn.f32x2 %0, %0, %1;" : "+l"(d) : "l"(a));
}

// ---------------------------------------------------------------------------
// SGEMM: out = A(8192x1024) @ W(1024x1024) + bias
// BM=BN=128, BK=16, 256 threads, 8x8 per thread, FFMA2 inner loop.
// out_mode 0: row-major (B*T, C). out_mode 1: scatter to (B,H,T,D).
// ---------------------------------------------------------------------------
__global__ __launch_bounds__(256)
void sgemm128(const float* __restrict__ A, const float* __restrict__ W,
              const float* __restrict__ bias, float* __restrict__ out,
              int out_mode)
{
    __shared__ float As[16][132];   // A^T tile, padded (row start 16B-aligned: 132*4=528=33*16)
    __shared__ float Bs[16][128];

    const int tid = threadIdx.x;
    const int bx = blockIdx.x;      // N block (0..7)
    const int by = blockIdx.y;      // M block (0..63)

    const float* Ab = A + (size_t)by * 128 * Cc;
    const float* Wb = W + bx * 128;

    const int row0 = (tid >> 4) * 8;
    const int col0 = (tid & 15) * 8;

    // acc2[p][j]: rows (row0+2p, row0+2p+1), col col0+j
    u64t acc2[4][8];
    #pragma unroll
    for (int p = 0; p < 4; p++)
        #pragma unroll
        for (int j = 0; j < 8; j++) acc2[p][j] = 0ull;

    for (int kt = 0; kt < Cc; kt += 16) {
        // Load A tile (128x16), transpose into As
        #pragma unroll
        for (int l = 0; l < 2; l++) {
            int s  = tid + l * 256;          // 0..511 float4 slots
            int ar = s >> 2;
            int ac = (s & 3) * 4;
            float4 t = *(const float4*)(Ab + (size_t)ar * Cc + kt + ac);
            As[ac + 0][ar] = t.x;
            As[ac + 1][ar] = t.y;
            As[ac + 2][ar] = t.z;
            As[ac + 3][ar] = t.w;
        }
        // Load W tile (16x128)
        #pragma unroll
        for (int l = 0; l < 2; l++) {
            int s  = tid + l * 256;
            int br = s >> 5;
            int bc = (s & 31) * 4;
            *(float4*)(&Bs[br][bc]) = *(const float4*)(Wb + (size_t)(kt + br) * Cc + bc);
        }
        __syncthreads();

        #pragma unroll
        for (int kk = 0; kk < 16; kk++) {
            // A row-pairs: 8 consecutive rows -> 4 packed u64
            const ulonglong2* ap = (const ulonglong2*)(&As[kk][row0]);
            ulonglong2 a01 = ap[0];     // rows 0-1, 2-3
            ulonglong2 a23 = ap[1];     // rows 4-5, 6-7
            float b[8];
            *(float4*)(b)     = *(const float4*)(&Bs[kk][col0]);
            *(float4*)(b + 4) = *(const float4*)(&Bs[kk][col0 + 4]);
            #pragma unroll
            for (int j = 0; j < 8; j++) {
                u64t bb = pk(b[j]);
                fma2(acc2[0][j], a01.x, bb);
                fma2(acc2[1][j], a01.y, bb);
                fma2(acc2[2][j], a23.x, bb);
                fma2(acc2[3][j], a23.y, bb);
            }
        }
        __syncthreads();
    }

    const int gm0 = by * 128 + row0;
    const int gn0 = bx * 128 + col0;
    float bv[8];
    #pragma unroll
    for (int j = 0; j < 8; j++) bv[j] = bias[gn0 + j];

    if (out_mode == 0) {
        #pragma unroll
        for (int p = 0; p < 4; p++)
            #pragma unroll
            for (int h2 = 0; h2 < 2; h2++) {
                int m = gm0 + 2 * p + h2;
                float r[8];
                #pragma unroll
                for (int j = 0; j < 8; j++) { F2 u; u.u = acc2[p][j]; r[j] = u.f[h2] + bv[j]; }
                *(float4*)(out + (size_t)m * Cc + gn0)     = make_float4(r[0], r[1], r[2], r[3]);
                *(float4*)(out + (size_t)m * Cc + gn0 + 4) = make_float4(r[4], r[5], r[6], r[7]);
            }
    } else {
        // scatter to (B,H,T,D): m = b*T + t ; n = h*D + d (8 cols stay in one h)
        const int h  = gn0 >> 6;
        const int d0 = gn0 & 63;
        #pragma unroll
        for (int p = 0; p < 4; p++)
            #pragma unroll
            for (int h2 = 0; h2 < 2; h2++) {
                int m = gm0 + 2 * p + h2;
                int b = m >> 11;          // /T
                int t = m & 2047;         // %T
                size_t base = (((size_t)(b * Hh + h)) * Tt + t) * Dd + d0;
                float r[8];
                #pragma unroll
                for (int j = 0; j < 8; j++) { F2 u; u.u = acc2[p][j]; r[j] = u.f[h2] + bv[j]; }
                *(float4*)(out + base)     = make_float4(r[0], r[1], r[2], r[3]);
                *(float4*)(out + base + 4) = make_float4(r[4], r[5], r[6], r[7]);
            }
    }
}

// ---------------------------------------------------------------------------
// Flash attention (fp32, causal), FFMA2 inner loops.
// One CTA = 64 query rows of one (b,h). 128 threads as (ty 0..7) x (tx 0..15);
// each thread owns 8 rows x 4 cols.
// Smem: Qt, Kt (d-major / transposed), Vs (kv-major), Pt (kv-major, i.e. P^T).
// ---------------------------------------------------------------------------
#define LDT 68
#define ATTN_SMEM (4 * 64 * LDT * (int)sizeof(float))   // 69,632 B

__global__ __launch_bounds__(128)
void attn_kernel(const float* __restrict__ q, const float* __restrict__ k,
                 const float* __restrict__ v, float* __restrict__ y)
{
    extern __shared__ float sm[];
    float* Qt = sm;                 // [d][row]   64 x LDT
    float* Kt = Qt + 64 * LDT;      // [d][col]   64 x LDT
    float* Vs = Kt + 64 * LDT;      // [kv][d]    64 x LDT
    float* Pt = Vs + 64 * LDT;      // [kv][row]  64 x LDT  (P transposed)

    const int qb  = blockIdx.x;     // query tile (0..31)
    const int bh  = blockIdx.y;     // 0..63
    const int tid = threadIdx.x;
    const int tx  = tid & 15;
    const int ty  = tid >> 4;       // 0..7
    const int r0  = ty * 8;
    const int c0  = tx * 4;

    const float* qp = q + ((size_t)bh * Tt + qb * 64) * Dd;
    const float* kp = k + (size_t)bh * Tt * Dd;
    const float* vp = v + (size_t)bh * Tt * Dd;

    // Load Q tile transposed: Qt[d][row]
    for (int i = tid; i < 64 * 16; i += 128) {
        int row = i & 63;
        int d4  = (i >> 6) * 4;
        float4 t = *(const float4*)(qp + (size_t)row * Dd + d4);
        Qt[(d4 + 0) * LDT + row] = t.x;
        Qt[(d4 + 1) * LDT + row] = t.y;
        Qt[(d4 + 2) * LDT + row] = t.z;
        Qt[(d4 + 3) * LDT + row] = t.w;
    }

    u64t o2[4][4];                  // rows (r0+2p, r0+2p+1) x col (c0+j)
    float m_i[8], l_i[8];
    #pragma unroll
    for (int i = 0; i < 8; i++) { m_i[i] = -INFINITY; l_i[i] = 0.f; }
    #pragma unroll
    for (int p = 0; p < 4; p++)
        #pragma unroll
        for (int j = 0; j < 4; j++) o2[p][j] = 0ull;

    for (int jt = 0; jt <= qb; jt++) {
        __syncthreads();   // protect Kt/Vs/Pt from previous iteration readers

        // K tile transposed: Kt[d][col]
        for (int i = tid; i < 64 * 16; i += 128) {
            int row = i & 63;
            int d4  = (i >> 6) * 4;
            float4 t = *(const float4*)(kp + (size_t)(jt * 64 + row) * Dd + d4);
            Kt[(d4 + 0) * LDT + row] = t.x;
            Kt[(d4 + 1) * LDT + row] = t.y;
            Kt[(d4 + 2) * LDT + row] = t.z;
            Kt[(d4 + 3) * LDT + row] = t.w;
        }
        // V tile, natural layout (coalesced)
        for (int i = tid; i < 64 * 16; i += 128) {
            int row = i >> 4;
            int d4  = (i & 15) * 4;
            *(float4*)(Vs + row * LDT + d4) =
                *(const float4*)(vp + (size_t)(jt * 64 + row) * Dd + d4);
        }
        __syncthreads();

        // S = Q K^T  (row-paired FFMA2)
        u64t s2[4][4];
        #pragma unroll
        for (int p = 0; p < 4; p++)
            #pragma unroll
            for (int j = 0; j < 4; j++) s2[p][j] = 0ull;

        #pragma unroll 8
        for (int d = 0; d < 64; d++) {
            const ulonglong2* qa = (const ulonglong2*)(Qt + d * LDT + r0);
            ulonglong2 q01 = qa[0];   // rows (0,1),(2,3)
            ulonglong2 q23 = qa[1];   // rows (4,5),(6,7)
            float4 kv4 = *(const float4*)(Kt + d * LDT + c0);
            u64t b0 = pk(kv4.x), b1 = pk(kv4.y), b2 = pk(kv4.z), b3 = pk(kv4.w);
            fma2(s2[0][0], q01.x, b0); fma2(s2[0][1], q01.x, b1);
            fma2(s2[0][2], q01.x, b2); fma2(s2[0][3], q01.x, b3);
            fma2(s2[1][0], q01.y, b0); fma2(s2[1][1], q01.y, b1);
            fma2(s2[1][2], q01.y, b2); fma2(s2[1][3], q01.y, b3);
            fma2(s2[2][0], q23.x, b0); fma2(s2[2][1], q23.x, b1);
            fma2(s2[2][2], q23.x, b2); fma2(s2[2][3], q23.x, b3);
            fma2(s2[3][0], q23.y, b0); fma2(s2[3][1], q23.y, b1);
            fma2(s2[3][2], q23.y, b2); fma2(s2[3][3], q23.y, b3);
        }

        // Unpack + scale
        const float scale = 0.125f;   // 1/sqrt(64)
        float sc[8][4];
        #pragma unroll
        for (int p = 0; p < 4; p++)
            #pragma unroll
            for (int j = 0; j < 4; j++) {
                F2 u; u.u = s2[p][j];
                sc[2 * p + 0][j] = u.f[0] * scale;
                sc[2 * p + 1][j] = u.f[1] * scale;
            }

        if (jt == qb) {
            #pragma unroll
            for (int i = 0; i < 8; i++)
                #pragma unroll
                for (int j = 0; j < 4; j++)
                    if (c0 + j > r0 + i) sc[i][j] = -INFINITY;
        }

        // Online softmax (row state replicated across the 16 tx threads)
        float alpha[8];
        #pragma unroll
        for (int i = 0; i < 8; i++) {
            float mx = fmaxf(fmaxf(sc[i][0], sc[i][1]), fmaxf(sc[i][2], sc[i][3]));
            #pragma unroll
            for (int off = 8; off >= 1; off >>= 1)
                mx = fmaxf(mx, __shfl_xor_sync(0xffffffffu, mx, off, 16));
            float mnew = fmaxf(m_i[i], mx);
            alpha[i] = __expf(m_i[i] - mnew);
            float sum = 0.f;
            #pragma unroll
            for (int j = 0; j < 4; j++) {
                sc[i][j] = __expf(sc[i][j] - mnew);
                sum += sc[i][j];
            }
            #pragma unroll
            for (int off = 8; off >= 1; off >>= 1)
                sum += __shfl_xor_sync(0xffffffffu, sum, off, 16);
            l_i[i] = l_i[i] * alpha[i] + sum;
            m_i[i] = mnew;
        }
        #pragma unroll
        for (int p = 0; p < 4; p++) {
            u64t ap = pk2(alpha[2 * p], alpha[2 * p + 1]);
            #pragma unroll
            for (int j = 0; j < 4; j++) mul2(o2[p][j], ap);
        }

        // Stage P transposed: Pt[kv][row], row-pairs as 64-bit stores
        #pragma unroll
        for (int j = 0; j < 4; j++)
            #pragma unroll
            for (int p = 0; p < 4; p++)
                *(u64t*)(Pt + (c0 + j) * LDT + r0 + 2 * p) =
                    pk2(sc[2 * p][j], sc[2 * p + 1][j]);
        __syncthreads();

        // O += P @ V  (row-paired FFMA2)
        #pragma unroll 8
        for (int kv = 0; kv < 64; kv++) {
            const ulonglong2* pa = (const ulonglong2*)(Pt + kv * LDT + r0);
            ulonglong2 p01 = pa[0];
            ulonglong2 p23 = pa[1];
            float4 vv = *(const float4*)(Vs + kv * LDT + c0);
            u64t b0 = pk(vv.x), b1 = pk(vv.y), b2 = pk(vv.z), b3 = pk(vv.w);
            fma2(o2[0][0], p01.x, b0); fma2(o2[0][1], p01.x, b1);
            fma2(o2[0][2], p01.x, b2); fma2(o2[0][3], p01.x, b3);
            fma2(o2[1][0], p01.y, b0); fma2(o2[1][1], p01.y, b1);
            fma2(o2[1][2], p01.y, b2); fma2(o2[1][3], p01.y, b3);
            fma2(o2[2][0], p23.x, b0); fma2(o2[2][1], p23.x, b1);
            fma2(o2[2][2], p23.x, b2); fma2(o2[2][3], p23.x, b3);
            fma2(o2[3][0], p23.y, b0); fma2(o2[3][1], p23.y, b1);
            fma2(o2[3][2], p23.y, b2); fma2(o2[3][3], p23.y, b3);
        }
    }

    // Epilogue: y[b, t, h*D + d] = O / l
    const int b = bh >> 4;
    const int h = bh & 15;
    #pragma unroll
    for (int p = 0; p < 4; p++)
        #pragma unroll
        for (int h2 = 0; h2 < 2; h2++) {
            int i = 2 * p + h2;
            int t = qb * 64 + r0 + i;
            float inv = 1.0f / l_i[i];
            float r[4];
            #pragma unroll
            for (int j = 0; j < 4; j++) { F2 u; u.u = o2[p][j]; r[j] = u.f[h2] * inv; }
            *(float4*)(y + ((size_t)(b * Tt + t)) * Cc + h * Dd + c0) =
                make_float4(r[0], r[1], r[2], r[3]);
        }
}

// ---------------------------------------------------------------------------
extern "C" void kernel_launch(void* const* d_in, const int* in_sizes, int n_in,
                              void* d_out, int out_size)
{
    const float* x  = (const float*)d_in[0];
    const float* wq = (const float*)d_in[1];
    const float* bq = (const float*)d_in[2];
    const float* wk = (const float*)d_in[3];
    const float* bk = (const float*)d_in[4];
    const float* wv = (const float*)d_in[5];
    const float* bv = (const float*)d_in[6];
    const float* wp = (const float*)d_in[7];
    const float* bp = (const float*)d_in[8];

    float* out   = (float*)d_out;
    float* y_out = out;                 // (B,T,C)
    float* k_out = out + YSZ;           // present[0] = k, (B,H,T,D)
    float* v_out = out + YSZ + KVSZ;    // present[1] = v

    float* qbuf;  cudaGetSymbolAddress((void**)&qbuf, g_q);
    float* ybuf;  cudaGetSymbolAddress((void**)&ybuf, g_y);

    cudaFuncSetAttribute(attn_kernel,
                         cudaFuncAttributeMaxDynamicSharedMemorySize, ATTN_SMEM);

    dim3 gG(Cc / 128, Mrows / 128);     // (8, 64)
    sgemm128<<<gG, 256>>>(x, wq, bq, qbuf, 1);
    sgemm128<<<gG, 256>>>(x, wk, bk, k_out, 1);
    sgemm128<<<gG, 256>>>(x, wv, bv, v_out, 1);

    dim3 gA(Tt / 64, Bb * Hh);          // (32, 64)
    attn_kernel<<<gA, 128, ATTN_SMEM>>>(qbuf, k_out, v_out, ybuf);

    sgemm128<<<gG, 256>>>(ybuf, wp, bp, y_out, 0);
}